// round 10
// baseline (speedup 1.0000x reference)
#include <cuda_runtime.h>
#include <cuda_bf16.h>
#include <cstdint>

// ============================ problem constants ============================
#define HDIM 256
#define SDIM 512
#define BDIM 2048
#define CDIM 10
#define BT   16
#define NCTA (BDIM / BT)        // 128
#define NTHR 256                // 8 warps, each owns m=32 (two m16 tiles)

// ============================ SMEM layout (bytes) ==========================
// W_lo SMEM half (kk 8-15): [8 warps][2 mtiles][8 kk][32 lanes][16B] = 65536
#define WLO_OFF 0
#define WLO_SZ  65536
// h tiles, [k=256][n=16] bf16, 48B rows: hi0, lo0, hi1, lo1
#define HROW    48
#define HTILE   (HDIM * HROW)            // 12288
#define HB_OFF  WLO_SZ                   // 65536
#define HB_SZ   (4 * HTILE)              // 49152
// x staged [n=16][t=512] fp32, row pad 516 floats
#define XROW    516
#define XS_OFF  (HB_OFF + HB_SZ)         // 114688
#define XS_SZ   (BT * XROW * 4)          // 33024
#define SMEM_SZ (XS_OFF + XS_SZ)         // 147712

// ============================ device helpers ===============================
__device__ __forceinline__ uint32_t smem_u32(const void* p) {
    return (uint32_t)__cvta_generic_to_shared(p);
}

// x2 trans ldmatrix: 2 mats = k-halves of one n8 tile
__device__ __forceinline__ void ldsm_x2_t(uint32_t* r, uint32_t addr) {
    asm volatile("ldmatrix.sync.aligned.m8n8.x2.trans.shared.b16 "
                 "{%0,%1}, [%2];"
                 : "=r"(r[0]), "=r"(r[1]) : "r"(addr));
}

__device__ __forceinline__ void mma16816(float* d, const uint32_t* a,
                                         uint32_t b0, uint32_t b1) {
    asm volatile("mma.sync.aligned.m16n8k16.row.col.f32.bf16.bf16.f32 "
                 "{%0,%1,%2,%3},{%4,%5,%6,%7},{%8,%9},{%0,%1,%2,%3};"
                 : "+f"(d[0]), "+f"(d[1]), "+f"(d[2]), "+f"(d[3])
                 : "r"(a[0]), "r"(a[1]), "r"(a[2]), "r"(a[3]),
                   "r"(b0), "r"(b1));
}

// split float pair into bf16-hi pair (x low half) + bf16-lo residual pair
__device__ __forceinline__ uint32_t split2(float x, float y, uint32_t& lo) {
    uint32_t hi;
    asm("cvt.rn.bf16x2.f32 %0, %1, %2;" : "=r"(hi) : "f"(y), "f"(x));
    float fx = __uint_as_float(hi << 16);
    float fy = __uint_as_float(hi & 0xffff0000u);
    float rx = x - fx, ry = y - fy;
    asm("cvt.rn.bf16x2.f32 %0, %1, %2;" : "=r"(lo) : "f"(ry), "f"(rx));
    return hi;
}

// paired tanh: one rcp serves two values. Upper clamp keeps d0*d1 finite.
__device__ __forceinline__ void tanh2(float a, float b, float& ta, float& tb) {
    a = fminf(a, 22.0f);
    b = fminf(b, 22.0f);
    float ea = __expf(a + a), eb = __expf(b + b);
    float da = ea + 1.0f,     db = eb + 1.0f;
    float r;
    asm("rcp.approx.f32 %0, %1;" : "=f"(r) : "f"(da * db));
    ta = fmaf(-2.0f * db, r, 1.0f);
    tb = fmaf(-2.0f * da, r, 1.0f);
}

// ---- one half-step GEMM: ntile base address HQ (hi tile), accs ACC[8] ----
#define ISSUE_HALF(HQ, ACC)                                                   \
do {                                                                          \
    _Pragma("unroll")                                                         \
    for (int _i = 0; _i < 8; ++_i) (ACC)[_i] = 0.0f;                          \
    const uint32_t _hhi = (HQ);                                               \
    const uint32_t _hlo = _hhi + HTILE;                                       \
    uint32_t _bh[2][2], _bl[2][2];                                            \
    ldsm_x2_t(_bh[0], _hhi);                                                  \
    ldsm_x2_t(_bl[0], _hlo);                                                  \
    _Pragma("unroll")                                                         \
    for (int kk = 0; kk < 16; ++kk) {                                         \
        const int cu = kk & 1, nx = cu ^ 1;                                   \
        if (kk < 15) {                                                        \
            ldsm_x2_t(_bh[nx], _hhi + (uint32_t)(kk + 1) * (16 * HROW));      \
            ldsm_x2_t(_bl[nx], _hlo + (uint32_t)(kk + 1) * (16 * HROW));      \
        }                                                                     \
        uint32_t _wA[4], _wB[4];                                              \
        if (kk < 8) {                                                         \
            _wA[0]=wloR[kk*4+0]; _wA[1]=wloR[kk*4+1];                         \
            _wA[2]=wloR[kk*4+2]; _wA[3]=wloR[kk*4+3];                         \
            _wB[0]=wloR[32+kk*4+0]; _wB[1]=wloR[32+kk*4+1];                   \
            _wB[2]=wloR[32+kk*4+2]; _wB[3]=wloR[32+kk*4+3];                   \
        } else {                                                              \
            uint4 _a4 = *reinterpret_cast<const uint4*>(wloSA + (kk-8)*512);  \
            uint4 _b4 = *reinterpret_cast<const uint4*>(wloSB + (kk-8)*512);  \
            _wA[0]=_a4.x; _wA[1]=_a4.y; _wA[2]=_a4.z; _wA[3]=_a4.w;           \
            _wB[0]=_b4.x; _wB[1]=_b4.y; _wB[2]=_b4.z; _wB[3]=_b4.w;           \
        }                                                                     \
        mma16816((ACC),     whi + kk*4,      _bh[cu][0], _bh[cu][1]);         \
        mma16816((ACC) + 4, whi + 64 + kk*4, _bh[cu][0], _bh[cu][1]);         \
        mma16816((ACC),     whi + kk*4,      _bl[cu][0], _bl[cu][1]);         \
        mma16816((ACC) + 4, whi + 64 + kk*4, _bl[cu][0], _bl[cu][1]);         \
        mma16816((ACC),     _wA,             _bh[cu][0], _bh[cu][1]);         \
        mma16816((ACC) + 4, _wB,             _bh[cu][0], _bh[cu][1]);         \
    }                                                                         \
} while (0)

// ---- half epilogue: ntile Q, x column T, dest hi-tile pointer OHI ----
#define EPI_HALF(ACC, Q, T, OHI)                                              \
do {                                                                          \
    const float _x0 = xs[((Q)*8 + cc)     * XROW + (T)];                      \
    const float _x1 = xs[((Q)*8 + cc + 1) * XROW + (T)];                      \
    char* _oh = (OHI);                                                        \
    char* _ol = _oh + HTILE;                                                  \
    const int _co = 16*(Q) + 4*tIG;                                           \
    float _t0, _t1; uint32_t _hi, _lo;                                        \
    tanh2((ACC)[0] + fmaf(wxA0, _x0, bhA0),                                   \
          (ACC)[1] + fmaf(wxA0, _x1, bhA0), _t0, _t1);                        \
    _hi = split2(_t0, _t1, _lo);                                              \
    *reinterpret_cast<uint32_t*>(_oh + rA0 * HROW + _co) = _hi;               \
    *reinterpret_cast<uint32_t*>(_ol + rA0 * HROW + _co) = _lo;               \
    tanh2((ACC)[2] + fmaf(wxA1, _x0, bhA1),                                   \
          (ACC)[3] + fmaf(wxA1, _x1, bhA1), _t0, _t1);                        \
    _hi = split2(_t0, _t1, _lo);                                              \
    *reinterpret_cast<uint32_t*>(_oh + rA1 * HROW + _co) = _hi;               \
    *reinterpret_cast<uint32_t*>(_ol + rA1 * HROW + _co) = _lo;               \
    tanh2((ACC)[4] + fmaf(wxB0, _x0, bhB0),                                   \
          (ACC)[5] + fmaf(wxB0, _x1, bhB0), _t0, _t1);                        \
    _hi = split2(_t0, _t1, _lo);                                              \
    *reinterpret_cast<uint32_t*>(_oh + rB0 * HROW + _co) = _hi;               \
    *reinterpret_cast<uint32_t*>(_ol + rB0 * HROW + _co) = _lo;               \
    tanh2((ACC)[6] + fmaf(wxB1, _x0, bhB1),                                   \
          (ACC)[7] + fmaf(wxB1, _x1, bhB1), _t0, _t1);                        \
    _hi = split2(_t0, _t1, _lo);                                              \
    *reinterpret_cast<uint32_t*>(_oh + rB1 * HROW + _co) = _hi;               \
    *reinterpret_cast<uint32_t*>(_ol + rB1 * HROW + _co) = _lo;               \
} while (0)

// ============================ kernel =======================================
extern "C" __global__ void __launch_bounds__(NTHR, 1)
rnn_split_kernel(const float* __restrict__ x,
                 const float* __restrict__ W_hx,
                 const float* __restrict__ W_hh,
                 const float* __restrict__ W_ph,
                 const float* __restrict__ b_h,
                 const float* __restrict__ b_p,
                 float* __restrict__ out)
{
    extern __shared__ char sm[];
    const uint32_t smu = smem_u32(sm);

    const int tid  = threadIdx.x;
    const int w    = tid >> 5;
    const int lane = tid & 31;
    const int g    = lane >> 2;
    const int tIG  = lane & 3;
    const int m0   = w * 32;
    const int c0   = blockIdx.x * BT;

    // ---- stage x ----
    {
        float* xsw = (float*)(sm + XS_OFF);
        #pragma unroll 1
        for (int idx = tid; idx < BT * SDIM / 4; idx += NTHR) {
            int n = idx >> 7, t4 = idx & 127;
            float4 v = *reinterpret_cast<const float4*>(
                x + (size_t)(c0 + n) * SDIM + t4 * 4);
            *reinterpret_cast<float4*>(xsw + n * XROW + t4 * 4) = v;
        }
    }
    // ---- zero h buffer 0 (hi0 + lo0) ----
    {
        uint4 z = {0u, 0u, 0u, 0u};
        #pragma unroll 1
        for (int idx = tid; idx < 2 * HTILE / 16; idx += NTHR)
            *reinterpret_cast<uint4*>(sm + HB_OFF + idx * 16) = z;
    }

    // ---- gather W_hh fragments ----
    uint32_t whi[128];                   // [mtile][kk][4]
    uint32_t wloR[64];                   // [mtile][kk<8][4]
    {
        #pragma unroll
        for (int tl = 0; tl < 2; ++tl) {
            const int rA = m0 + tl * 16 + g;
            const int rB = rA + 8;
            const float* Wr0 = W_hh + (size_t)rA * HDIM;
            const float* Wr1 = W_hh + (size_t)rB * HDIM;
            char* wlo_base = sm + WLO_OFF +
                ((size_t)(w * 2 + tl) * 8) * 512 + (size_t)lane * 16;
            #pragma unroll
            for (int kk = 0; kk < 16; ++kk) {
                int cl = kk * 16 + 2 * tIG;
                int ch = cl + 8;
                float2 w00 = *reinterpret_cast<const float2*>(Wr0 + cl);
                float2 w10 = *reinterpret_cast<const float2*>(Wr1 + cl);
                float2 w01 = *reinterpret_cast<const float2*>(Wr0 + ch);
                float2 w11 = *reinterpret_cast<const float2*>(Wr1 + ch);
                uint4 lo;
                whi[tl * 64 + kk * 4 + 0] = split2(w00.x, w00.y, lo.x);
                whi[tl * 64 + kk * 4 + 1] = split2(w10.x, w10.y, lo.y);
                whi[tl * 64 + kk * 4 + 2] = split2(w01.x, w01.y, lo.z);
                whi[tl * 64 + kk * 4 + 3] = split2(w11.x, w11.y, lo.w);
                if (kk < 8) {
                    wloR[tl * 32 + kk * 4 + 0] = lo.x;
                    wloR[tl * 32 + kk * 4 + 1] = lo.y;
                    wloR[tl * 32 + kk * 4 + 2] = lo.z;
                    wloR[tl * 32 + kk * 4 + 3] = lo.w;
                } else {
                    *reinterpret_cast<uint4*>(wlo_base + (size_t)(kk - 8) * 512) = lo;
                }
            }
        }
    }

    // epilogue constants
    const int rA0 = m0 + g, rA1 = rA0 + 8, rB0 = rA0 + 16, rB1 = rA0 + 24;
    const float wxA0 = W_hx[rA0], wxA1 = W_hx[rA1];
    const float wxB0 = W_hx[rB0], wxB1 = W_hx[rB1];
    const float bhA0 = b_h[rA0],  bhA1 = b_h[rA1];
    const float bhB0 = b_h[rB0],  bhB1 = b_h[rB1];

    // x2 ldmatrix per-thread offset within an h tile (lanes 0-15 live)
    const uint32_t lm2 = (uint32_t)((lane & 15) * HROW);
    const uint32_t hb_u32 = smu + HB_OFF;
    const char* wloSA = sm + WLO_OFF + ((size_t)(w * 2) * 8) * 512 + (size_t)lane * 16;
    const char* wloSB = wloSA + 8 * 512;
    const float* xs = (const float*)(sm + XS_OFF);
    const int cc = 2 * tIG;

    __syncthreads();

    float acc0[8], acc1[8];

    // ======================= split-step time loop =======================
    // invariant at loop top (iteration t): acc0/acc1 = W·h(t), h(t) in buf t&1
    ISSUE_HALF(hb_u32 + 0 * (2 * HTILE) + 0  + lm2, acc0);   // ntile0, buf0
    ISSUE_HALF(hb_u32 + 0 * (2 * HTILE) + 16 + lm2, acc1);   // ntile1, buf0

    #pragma unroll 1
    for (int t = 0; t < SDIM - 1; ++t) {
        const uint32_t nb = (uint32_t)((t + 1) & 1);          // buf of h(t+1)
        char* ohi = sm + HB_OFF + nb * 2 * HTILE;
        EPI_HALF(acc0, 0, t, ohi);                            // write h(t+1) ntile0
        __syncthreads();                                      // barA
        ISSUE_HALF(hb_u32 + nb * 2 * HTILE + 0 + lm2, acc0);  // W·h(t+1) ntile0
        EPI_HALF(acc1, 1, t, ohi);                            // h(t+1) ntile1
        __syncthreads();                                      // barB
        ISSUE_HALF(hb_u32 + nb * 2 * HTILE + 16 + lm2, acc1); // W·h(t+1) ntile1
    }
    // final epilogue: h(512) -> buf 0
    {
        char* ohi = sm + HB_OFF;                              // (512)&1 = 0
        EPI_HALF(acc0, 0, SDIM - 1, ohi);
        EPI_HALF(acc1, 1, SDIM - 1, ohi);
    }
    __syncthreads();

    // ======================= final projection =======================
    if (tid < BT * CDIM) {
        const int b = tid / CDIM, c = tid % CDIM;
        const char* hb = sm + HB_OFF;
        const char* lb = hb + HTILE;
        float s = b_p[c];
        #pragma unroll 4
        for (int i = 0; i < HDIM; ++i) {
            float h = __bfloat162float(*reinterpret_cast<const __nv_bfloat16*>(
                          hb + i * HROW + 2 * b))
                    + __bfloat162float(*reinterpret_cast<const __nv_bfloat16*>(
                          lb + i * HROW + 2 * b));
            s += W_ph[c * HDIM + i] * h;
        }
        out[(size_t)(c0 + b) * CDIM + c] = s;
    }
}

extern "C" void kernel_launch(void* const* d_in, const int* in_sizes, int n_in,
                              void* d_out, int out_size)
{
    const float* x    = (const float*)d_in[0];
    const float* W_hx = (const float*)d_in[1];
    const float* W_hh = (const float*)d_in[2];
    const float* W_ph = (const float*)d_in[3];
    const float* b_h  = (const float*)d_in[4];
    const float* b_p  = (const float*)d_in[5];
    float* out = (float*)d_out;

    cudaFuncSetAttribute(rnn_split_kernel,
                         cudaFuncAttributeMaxDynamicSharedMemorySize, SMEM_SZ);
    rnn_split_kernel<<<NCTA, NTHR, SMEM_SZ>>>(x, W_hx, W_hh, W_ph, b_h, b_p, out);
}

// round 11
// speedup vs baseline: 1.0258x; 1.0258x over previous
#include <cuda_runtime.h>
#include <cuda_bf16.h>
#include <cstdint>

// ============================ problem constants ============================
#define HDIM 256
#define SDIM 512
#define BDIM 2048
#define CDIM 10
#define BT   16                 // batch columns per CTA (N)
#define NCTA (BDIM / BT)        // 128
#define NTHR 256                // 8 warps, each owns m=32 (two m16 tiles)

// ============================ SMEM layout (bytes) ==========================
// W_lo SMEM half (kk 8-15): [8 warps][2 mtiles][8 kk][32 lanes][16B] = 65536
#define WLO_OFF 0
#define WLO_SZ  65536
// h tiles, [k=256][n=16] bf16, 48B rows: hi0, lo0, hi1, lo1
#define HROW    48
#define HTILE   (HDIM * HROW)            // 12288
#define HB_OFF  WLO_SZ                   // 65536
#define HB_SZ   (4 * HTILE)              // 49152
// x staged [n=16][t=512] fp32, row pad 516 floats
#define XROW    516
#define XS_OFF  (HB_OFF + HB_SZ)         // 114688
#define XS_SZ   (BT * XROW * 4)          // 33024
#define SMEM_SZ (XS_OFF + XS_SZ)         // 147712

// ============================ device helpers ===============================
__device__ __forceinline__ uint32_t smem_u32(const void* p) {
    return (uint32_t)__cvta_generic_to_shared(p);
}

__device__ __forceinline__ void ldsm_x4_t(uint32_t* r, uint32_t addr) {
    asm volatile("ldmatrix.sync.aligned.m8n8.x4.trans.shared.b16 "
                 "{%0,%1,%2,%3}, [%4];"
                 : "=r"(r[0]), "=r"(r[1]), "=r"(r[2]), "=r"(r[3])
                 : "r"(addr));
}

__device__ __forceinline__ void mma16816(float* d, const uint32_t* a,
                                         uint32_t b0, uint32_t b1) {
    asm volatile("mma.sync.aligned.m16n8k16.row.col.f32.bf16.bf16.f32 "
                 "{%0,%1,%2,%3},{%4,%5,%6,%7},{%8,%9},{%0,%1,%2,%3};"
                 : "+f"(d[0]), "+f"(d[1]), "+f"(d[2]), "+f"(d[3])
                 : "r"(a[0]), "r"(a[1]), "r"(a[2]), "r"(a[3]),
                   "r"(b0), "r"(b1));
}

// split float pair into bf16-hi pair (x low half) + bf16-lo residual pair
__device__ __forceinline__ uint32_t split2(float x, float y, uint32_t& lo) {
    uint32_t hi;
    asm("cvt.rn.bf16x2.f32 %0, %1, %2;" : "=r"(hi) : "f"(y), "f"(x));
    float fx = __uint_as_float(hi << 16);
    float fy = __uint_as_float(hi & 0xffff0000u);
    float rx = x - fx, ry = y - fy;
    asm("cvt.rn.bf16x2.f32 %0, %1, %2;" : "=r"(lo) : "f"(ry), "f"(rx));
    return hi;
}

// paired tanh: one rcp serves two values (validated round 10).
// Upper clamp 22 keeps da*db finite; -inf side is naturally safe.
__device__ __forceinline__ void tanh2(float a, float b, float& ta, float& tb) {
    a = fminf(a, 22.0f);
    b = fminf(b, 22.0f);
    float ea = __expf(a + a), eb = __expf(b + b);
    float da = ea + 1.0f,     db = eb + 1.0f;
    float r;
    asm("rcp.approx.f32 %0, %1;" : "=f"(r) : "f"(da * db));
    ta = fmaf(-2.0f * db, r, 1.0f);
    tb = fmaf(-2.0f * da, r, 1.0f);
}

// ============================ kernel =======================================
extern "C" __global__ void __launch_bounds__(NTHR, 1)
rnn_hmma11_kernel(const float* __restrict__ x,
                  const float* __restrict__ W_hx,
                  const float* __restrict__ W_hh,
                  const float* __restrict__ W_ph,
                  const float* __restrict__ b_h,
                  const float* __restrict__ b_p,
                  float* __restrict__ out)
{
    extern __shared__ char sm[];
    const uint32_t smu = smem_u32(sm);

    const int tid  = threadIdx.x;
    const int w    = tid >> 5;          // warp id, owns rows 32w..32w+31
    const int lane = tid & 31;
    const int g    = lane >> 2;         // groupID 0..7
    const int tIG  = lane & 3;          // thread-in-group 0..3
    const int m0   = w * 32;
    const int c0   = blockIdx.x * BT;

    // ---- stage x: xs[n][t] fp32, coalesced float4 ----
    {
        float* xsw = (float*)(sm + XS_OFF);
        #pragma unroll 1
        for (int idx = tid; idx < BT * SDIM / 4; idx += NTHR) {
            int n = idx >> 7, t4 = idx & 127;
            float4 v = *reinterpret_cast<const float4*>(
                x + (size_t)(c0 + n) * SDIM + t4 * 4);
            *reinterpret_cast<float4*>(xsw + n * XROW + t4 * 4) = v;
        }
    }
    // ---- zero h buffer 0 (hi0 + lo0) ----
    {
        uint4 z = {0u, 0u, 0u, 0u};
        #pragma unroll 1
        for (int idx = tid; idx < 2 * HTILE / 16; idx += NTHR)
            *reinterpret_cast<uint4*>(sm + HB_OFF + idx * 16) = z;
    }

    // ---- gather W_hh fragments: hi -> regs; lo kk<8 -> regs, kk>=8 -> SMEM --
    uint32_t whi[128];                   // [mtile][kk][4]
    uint32_t wloR[64];                   // [mtile][kk<8][4]
    {
        #pragma unroll
        for (int tl = 0; tl < 2; ++tl) {
            const int rA = m0 + tl * 16 + g;
            const int rB = rA + 8;
            const float* Wr0 = W_hh + (size_t)rA * HDIM;
            const float* Wr1 = W_hh + (size_t)rB * HDIM;
            char* wlo_base = sm + WLO_OFF +
                ((size_t)(w * 2 + tl) * 8) * 512 + (size_t)lane * 16;
            #pragma unroll
            for (int kk = 0; kk < 16; ++kk) {
                int cl = kk * 16 + 2 * tIG;
                int ch = cl + 8;
                float2 w00 = *reinterpret_cast<const float2*>(Wr0 + cl);
                float2 w10 = *reinterpret_cast<const float2*>(Wr1 + cl);
                float2 w01 = *reinterpret_cast<const float2*>(Wr0 + ch);
                float2 w11 = *reinterpret_cast<const float2*>(Wr1 + ch);
                uint4 lo;
                whi[tl * 64 + kk * 4 + 0] = split2(w00.x, w00.y, lo.x);
                whi[tl * 64 + kk * 4 + 1] = split2(w10.x, w10.y, lo.y);
                whi[tl * 64 + kk * 4 + 2] = split2(w01.x, w01.y, lo.z);
                whi[tl * 64 + kk * 4 + 3] = split2(w11.x, w11.y, lo.w);
                if (kk < 8) {
                    wloR[tl * 32 + kk * 4 + 0] = lo.x;
                    wloR[tl * 32 + kk * 4 + 1] = lo.y;
                    wloR[tl * 32 + kk * 4 + 2] = lo.z;
                    wloR[tl * 32 + kk * 4 + 3] = lo.w;
                } else {
                    *reinterpret_cast<uint4*>(wlo_base + (size_t)(kk - 8) * 512) = lo;
                }
            }
        }
    }

    // epilogue constants
    const int rA0 = m0 + g, rA1 = rA0 + 8, rB0 = rA0 + 16, rB1 = rA0 + 24;
    const float wxA0 = W_hx[rA0], wxA1 = W_hx[rA1];
    const float wxB0 = W_hx[rB0], wxB1 = W_hx[rB1];
    const float bhA0 = b_h[rA0],  bhA1 = b_h[rA1];
    const float bhB0 = b_h[rB0],  bhB1 = b_h[rB1];

    const uint32_t lm_off = (uint32_t)((((lane >> 3) & 1) * 8 + (lane & 7)) * HROW
                                       + ((lane >> 4) * 16));
    const uint32_t hb_u32 = smu + HB_OFF;
    const char* wloSA = sm + WLO_OFF + ((size_t)(w * 2) * 8) * 512 + (size_t)lane * 16;
    const char* wloSB = wloSA + 8 * 512;
    const float* xs = (const float*)(sm + XS_OFF);
    const int cc = 2 * tIG;

    __syncthreads();

    // ======================= time loop =======================
    #pragma unroll 1
    for (int t = 0; t < SDIM; ++t) {
        const int p = t & 1;
        const uint32_t hhi = hb_u32 + (uint32_t)(p * 2 * HTILE) + lm_off;
        const uint32_t hlo = hhi + HTILE;

        const float x00 = xs[(cc + 0) * XROW + t];
        const float x01 = xs[(cc + 1) * XROW + t];
        const float x08 = xs[(cc + 8) * XROW + t];
        const float x09 = xs[(cc + 9) * XROW + t];

        float DA0[4] = {0.f,0.f,0.f,0.f};
        float DA1[4] = {0.f,0.f,0.f,0.f};
        float DB0[4] = {0.f,0.f,0.f,0.f};
        float DB1[4] = {0.f,0.f,0.f,0.f};

        // -------- k-loop: depth-2 prefetch with 2 buffers, RR acc order -----
        uint32_t bhv[2][4], blv[2][4];
        uint4 wa[2], wb[2];               // W-SMEM prefetch, double-buffered
        ldsm_x4_t(bhv[0], hhi);
        ldsm_x4_t(blv[0], hlo);
        ldsm_x4_t(bhv[1], hhi + (uint32_t)(16 * HROW));
        ldsm_x4_t(blv[1], hlo + (uint32_t)(16 * HROW));

        #pragma unroll
        for (int kk = 0; kk < 16; ++kk) {
            const int cu = kk & 1, nx = cu ^ 1;
            if (kk >= 7 && kk < 15) {     // prefetch W_lo[kk+1] into other buf
                wa[nx] = *reinterpret_cast<const uint4*>(wloSA + (kk - 7) * 512);
                wb[nx] = *reinterpret_cast<const uint4*>(wloSB + (kk - 7) * 512);
            }
            uint32_t wloA[4], wloB[4];
            if (kk < 8) {
                wloA[0] = wloR[kk*4+0]; wloA[1] = wloR[kk*4+1];
                wloA[2] = wloR[kk*4+2]; wloA[3] = wloR[kk*4+3];
                wloB[0] = wloR[32+kk*4+0]; wloB[1] = wloR[32+kk*4+1];
                wloB[2] = wloR[32+kk*4+2]; wloB[3] = wloR[32+kk*4+3];
            } else {
                wloA[0]=wa[cu].x; wloA[1]=wa[cu].y; wloA[2]=wa[cu].z; wloA[3]=wa[cu].w;
                wloB[0]=wb[cu].x; wloB[1]=wb[cu].y; wloB[2]=wb[cu].z; wloB[3]=wb[cu].w;
            }
            const uint32_t* aA = whi + kk * 4;
            const uint32_t* aB = whi + 64 + kk * 4;
            const uint32_t* bh4 = bhv[cu];
            const uint32_t* bl4 = blv[cu];

            // --- all 8 bh-consumers first (RR across accs) ---
            mma16816(DA0, aA,   bh4[0], bh4[1]);
            mma16816(DA1, aA,   bh4[2], bh4[3]);
            mma16816(DB0, aB,   bh4[0], bh4[1]);
            mma16816(DB1, aB,   bh4[2], bh4[3]);
            mma16816(DA0, wloA, bh4[0], bh4[1]);
            mma16816(DA1, wloA, bh4[2], bh4[3]);
            mma16816(DB0, wloB, bh4[0], bh4[1]);
            mma16816(DB1, wloB, bh4[2], bh4[3]);
            // bh[cu] now dead: refill with kk+2 (prefetch distance ~1.5 kk)
            if (kk < 14)
                ldsm_x4_t(bhv[cu], hhi + (uint32_t)(kk + 2) * (16 * HROW));
            // --- 4 bl-consumers ---
            mma16816(DA0, aA,   bl4[0], bl4[1]);
            mma16816(DA1, aA,   bl4[2], bl4[3]);
            mma16816(DB0, aB,   bl4[0], bl4[1]);
            mma16816(DB1, aB,   bl4[2], bl4[3]);
            // bl[cu] dead: refill with kk+2
            if (kk < 14)
                ldsm_x4_t(blv[cu], hlo + (uint32_t)(kk + 2) * (16 * HROW));
        }

        // ---- epilogue (tanh2 pairs, ordered by acc completion) ----
        char* ohi = sm + HB_OFF + (p ^ 1) * 2 * HTILE;
        char* olo = ohi + HTILE;
        float t0, t1;
        uint32_t hi, lo;

        tanh2(DA0[0] + fmaf(wxA0, x00, bhA0),
              DA0[1] + fmaf(wxA0, x01, bhA0), t0, t1);
        hi = split2(t0, t1, lo);
        *reinterpret_cast<uint32_t*>(ohi + rA0 * HROW + 4 * tIG) = hi;
        *reinterpret_cast<uint32_t*>(olo + rA0 * HROW + 4 * tIG) = lo;
        tanh2(DA0[2] + fmaf(wxA1, x00, bhA1),
              DA0[3] + fmaf(wxA1, x01, bhA1), t0, t1);
        hi = split2(t0, t1, lo);
        *reinterpret_cast<uint32_t*>(ohi + rA1 * HROW + 4 * tIG) = hi;
        *reinterpret_cast<uint32_t*>(olo + rA1 * HROW + 4 * tIG) = lo;

        tanh2(DA1[0] + fmaf(wxA0, x08, bhA0),
              DA1[1] + fmaf(wxA0, x09, bhA0), t0, t1);
        hi = split2(t0, t1, lo);
        *reinterpret_cast<uint32_t*>(ohi + rA0 * HROW + 16 + 4 * tIG) = hi;
        *reinterpret_cast<uint32_t*>(olo + rA0 * HROW + 16 + 4 * tIG) = lo;
        tanh2(DA1[2] + fmaf(wxA1, x08, bhA1),
              DA1[3] + fmaf(wxA1, x09, bhA1), t0, t1);
        hi = split2(t0, t1, lo);
        *reinterpret_cast<uint32_t*>(ohi + rA1 * HROW + 16 + 4 * tIG) = hi;
        *reinterpret_cast<uint32_t*>(olo + rA1 * HROW + 16 + 4 * tIG) = lo;

        tanh2(DB0[0] + fmaf(wxB0, x00, bhB0),
              DB0[1] + fmaf(wxB0, x01, bhB0), t0, t1);
        hi = split2(t0, t1, lo);
        *reinterpret_cast<uint32_t*>(ohi + rB0 * HROW + 4 * tIG) = hi;
        *reinterpret_cast<uint32_t*>(olo + rB0 * HROW + 4 * tIG) = lo;
        tanh2(DB0[2] + fmaf(wxB1, x00, bhB1),
              DB0[3] + fmaf(wxB1, x01, bhB1), t0, t1);
        hi = split2(t0, t1, lo);
        *reinterpret_cast<uint32_t*>(ohi + rB1 * HROW + 4 * tIG) = hi;
        *reinterpret_cast<uint32_t*>(olo + rB1 * HROW + 4 * tIG) = lo;

        tanh2(DB1[0] + fmaf(wxB0, x08, bhB0),
              DB1[1] + fmaf(wxB0, x09, bhB0), t0, t1);
        hi = split2(t0, t1, lo);
        *reinterpret_cast<uint32_t*>(ohi + rB0 * HROW + 16 + 4 * tIG) = hi;
        *reinterpret_cast<uint32_t*>(olo + rB0 * HROW + 16 + 4 * tIG) = lo;
        tanh2(DB1[2] + fmaf(wxB1, x08, bhB1),
              DB1[3] + fmaf(wxB1, x09, bhB1), t0, t1);
        hi = split2(t0, t1, lo);
        *reinterpret_cast<uint32_t*>(ohi + rB1 * HROW + 16 + 4 * tIG) = hi;
        *reinterpret_cast<uint32_t*>(olo + rB1 * HROW + 16 + 4 * tIG) = lo;

        __syncthreads();
    }

    // ======================= final projection =======================
    if (tid < BT * CDIM) {
        const int b = tid / CDIM, c = tid % CDIM;
        const char* hb = sm + HB_OFF;
        const char* lb = hb + HTILE;
        float s = b_p[c];
        #pragma unroll 4
        for (int i = 0; i < HDIM; ++i) {
            float h = __bfloat162float(*reinterpret_cast<const __nv_bfloat16*>(
                          hb + i * HROW + 2 * b))
                    + __bfloat162float(*reinterpret_cast<const __nv_bfloat16*>(
                          lb + i * HROW + 2 * b));
            s += W_ph[c * HDIM + i] * h;
        }
        out[(size_t)(c0 + b) * CDIM + c] = s;
    }
}

extern "C" void kernel_launch(void* const* d_in, const int* in_sizes, int n_in,
                              void* d_out, int out_size)
{
    const float* x    = (const float*)d_in[0];
    const float* W_hx = (const float*)d_in[1];
    const float* W_hh = (const float*)d_in[2];
    const float* W_ph = (const float*)d_in[3];
    const float* b_h  = (const float*)d_in[4];
    const float* b_p  = (const float*)d_in[5];
    float* out = (float*)d_out;

    cudaFuncSetAttribute(rnn_hmma11_kernel,
                         cudaFuncAttributeMaxDynamicSharedMemorySize, SMEM_SZ);
    rnn_hmma11_kernel<<<NCTA, NTHR, SMEM_SZ>>>(x, W_hx, W_hh, W_ph, b_h, b_p, out);
}

// round 12
// speedup vs baseline: 1.0398x; 1.0136x over previous
#include <cuda_runtime.h>
#include <cuda_bf16.h>
#include <cstdint>

// ============================ problem constants ============================
#define HDIM 256
#define SDIM 512
#define BDIM 2048
#define CDIM 10
#define BT   16                 // batch columns per CTA (N)
#define NCTA (BDIM / BT)        // 128
#define NTHR 256                // 8 warps, each owns m=32 (two m16 tiles)

// ============================ SMEM layout (bytes) ==========================
// W_lo SMEM half (kk 8-15): [8 warps][2 mtiles][8 kk][32 lanes][16B] = 65536
#define WLO_OFF 0
#define WLO_SZ  65536
// h tiles, [k=256][n=16] bf16, 48B rows: hi0, lo0, hi1, lo1
#define HROW    48
#define HTILE   (HDIM * HROW)            // 12288
#define HB_OFF  WLO_SZ                   // 65536
#define HB_SZ   (4 * HTILE)              // 49152
// x staged [n=16][t=512] fp32, row pad 516 floats
#define XROW    516
#define XS_OFF  (HB_OFF + HB_SZ)         // 114688
#define XS_SZ   (BT * XROW * 4)          // 33024
#define SMEM_SZ (XS_OFF + XS_SZ)         // 147712

// ============================ device helpers ===============================
__device__ __forceinline__ uint32_t smem_u32(const void* p) {
    return (uint32_t)__cvta_generic_to_shared(p);
}

__device__ __forceinline__ void ldsm_x4_t(uint32_t* r, uint32_t addr) {
    asm volatile("ldmatrix.sync.aligned.m8n8.x4.trans.shared.b16 "
                 "{%0,%1,%2,%3}, [%4];"
                 : "=r"(r[0]), "=r"(r[1]), "=r"(r[2]), "=r"(r[3])
                 : "r"(addr));
}

__device__ __forceinline__ void mma16816(float* d, const uint32_t* a,
                                         uint32_t b0, uint32_t b1) {
    asm volatile("mma.sync.aligned.m16n8k16.row.col.f32.bf16.bf16.f32 "
                 "{%0,%1,%2,%3},{%4,%5,%6,%7},{%8,%9},{%0,%1,%2,%3};"
                 : "+f"(d[0]), "+f"(d[1]), "+f"(d[2]), "+f"(d[3])
                 : "r"(a[0]), "r"(a[1]), "r"(a[2]), "r"(a[3]),
                   "r"(b0), "r"(b1));
}

// split float pair into bf16-hi pair (x low half) + bf16-lo residual pair
__device__ __forceinline__ uint32_t split2(float x, float y, uint32_t& lo) {
    uint32_t hi;
    asm("cvt.rn.bf16x2.f32 %0, %1, %2;" : "=r"(hi) : "f"(y), "f"(x));
    float fx = __uint_as_float(hi << 16);
    float fy = __uint_as_float(hi & 0xffff0000u);
    float rx = x - fx, ry = y - fy;
    asm("cvt.rn.bf16x2.f32 %0, %1, %2;" : "=r"(lo) : "f"(ry), "f"(rx));
    return hi;
}

// quad tanh: one rcp serves four values. Clamp +10 keeps the 4-product
// finite (e^20^4 ~ 5e34 < fp32 max); tanh(10) = 1-8e-9 so clamp error ~1e-8.
__device__ __forceinline__ void tanh4(float* v) {
    const float C = 2.8853900817779268f;     // 2*log2(e)
    float u0 = fminf(v[0], 10.0f) * C;
    float u1 = fminf(v[1], 10.0f) * C;
    float u2 = fminf(v[2], 10.0f) * C;
    float u3 = fminf(v[3], 10.0f) * C;
    float d0 = exp2f(u0) + 1.0f;
    float d1 = exp2f(u1) + 1.0f;
    float d2 = exp2f(u2) + 1.0f;
    float d3 = exp2f(u3) + 1.0f;
    float m01 = d0 * d1, m23 = d2 * d3;
    float r;
    asm("rcp.approx.f32 %0, %1;" : "=f"(r) : "f"(m01 * m23));
    float r01 = r * m23, r23 = r * m01;      // 1/(d0 d1), 1/(d2 d3)
    v[0] = fmaf(r01 * d1, -2.0f, 1.0f);      // 1 - 2/d0
    v[1] = fmaf(r01 * d0, -2.0f, 1.0f);
    v[2] = fmaf(r23 * d3, -2.0f, 1.0f);
    v[3] = fmaf(r23 * d2, -2.0f, 1.0f);
}

// ============================ kernel =======================================
extern "C" __global__ void __launch_bounds__(NTHR, 1)
rnn_hmma12_kernel(const float* __restrict__ x,
                  const float* __restrict__ W_hx,
                  const float* __restrict__ W_hh,
                  const float* __restrict__ W_ph,
                  const float* __restrict__ b_h,
                  const float* __restrict__ b_p,
                  float* __restrict__ out)
{
    extern __shared__ char sm[];
    const uint32_t smu = smem_u32(sm);

    const int tid  = threadIdx.x;
    const int w    = tid >> 5;          // warp id, owns rows 32w..32w+31
    const int lane = tid & 31;
    const int g    = lane >> 2;         // groupID 0..7
    const int tIG  = lane & 3;          // thread-in-group 0..3
    const int m0   = w * 32;
    const int c0   = blockIdx.x * BT;

    // ---- stage x: xs[n][t] fp32, coalesced float4 ----
    {
        float* xsw = (float*)(sm + XS_OFF);
        #pragma unroll 1
        for (int idx = tid; idx < BT * SDIM / 4; idx += NTHR) {
            int n = idx >> 7, t4 = idx & 127;
            float4 v = *reinterpret_cast<const float4*>(
                x + (size_t)(c0 + n) * SDIM + t4 * 4);
            *reinterpret_cast<float4*>(xsw + n * XROW + t4 * 4) = v;
        }
    }
    // ---- zero h buffer 0 (hi0 + lo0) ----
    {
        uint4 z = {0u, 0u, 0u, 0u};
        #pragma unroll 1
        for (int idx = tid; idx < 2 * HTILE / 16; idx += NTHR)
            *reinterpret_cast<uint4*>(sm + HB_OFF + idx * 16) = z;
    }

    // ---- gather W_hh fragments: hi -> regs; lo kk<8 -> regs, kk>=8 -> SMEM --
    uint32_t whi[128];                   // [mtile][kk][4]
    uint32_t wloR[64];                   // [mtile][kk<8][4]
    {
        #pragma unroll
        for (int tl = 0; tl < 2; ++tl) {
            const int rA = m0 + tl * 16 + g;
            const int rB = rA + 8;
            const float* Wr0 = W_hh + (size_t)rA * HDIM;
            const float* Wr1 = W_hh + (size_t)rB * HDIM;
            char* wlo_base = sm + WLO_OFF +
                ((size_t)(w * 2 + tl) * 8) * 512 + (size_t)lane * 16;
            #pragma unroll
            for (int kk = 0; kk < 16; ++kk) {
                int cl = kk * 16 + 2 * tIG;
                int ch = cl + 8;
                float2 w00 = *reinterpret_cast<const float2*>(Wr0 + cl);
                float2 w10 = *reinterpret_cast<const float2*>(Wr1 + cl);
                float2 w01 = *reinterpret_cast<const float2*>(Wr0 + ch);
                float2 w11 = *reinterpret_cast<const float2*>(Wr1 + ch);
                uint4 lo;
                whi[tl * 64 + kk * 4 + 0] = split2(w00.x, w00.y, lo.x);
                whi[tl * 64 + kk * 4 + 1] = split2(w10.x, w10.y, lo.y);
                whi[tl * 64 + kk * 4 + 2] = split2(w01.x, w01.y, lo.z);
                whi[tl * 64 + kk * 4 + 3] = split2(w11.x, w11.y, lo.w);
                if (kk < 8) {
                    wloR[tl * 32 + kk * 4 + 0] = lo.x;
                    wloR[tl * 32 + kk * 4 + 1] = lo.y;
                    wloR[tl * 32 + kk * 4 + 2] = lo.z;
                    wloR[tl * 32 + kk * 4 + 3] = lo.w;
                } else {
                    *reinterpret_cast<uint4*>(wlo_base + (size_t)(kk - 8) * 512) = lo;
                }
            }
        }
    }

    // epilogue constants
    const int rA0 = m0 + g, rA1 = rA0 + 8, rB0 = rA0 + 16, rB1 = rA0 + 24;
    const float wxA0 = W_hx[rA0], wxA1 = W_hx[rA1];
    const float wxB0 = W_hx[rB0], wxB1 = W_hx[rB1];
    const float bhA0 = b_h[rA0],  bhA1 = b_h[rA1];
    const float bhB0 = b_h[rB0],  bhB1 = b_h[rB1];

    const uint32_t lm_off = (uint32_t)((((lane >> 3) & 1) * 8 + (lane & 7)) * HROW
                                       + ((lane >> 4) * 16));
    const uint32_t hb_u32 = smu + HB_OFF;
    const char* wloSA = sm + WLO_OFF + ((size_t)(w * 2) * 8) * 512 + (size_t)lane * 16;
    const char* wloSB = wloSA + 8 * 512;
    const float* xs = (const float*)(sm + XS_OFF);
    const int cc = 2 * tIG;

    __syncthreads();

    // ======================= time loop =======================
    #pragma unroll 1
    for (int t = 0; t < SDIM; ++t) {
        const int p = t & 1;
        const uint32_t hhi = hb_u32 + (uint32_t)(p * 2 * HTILE) + lm_off;
        const uint32_t hlo = hhi + HTILE;

        const float x00 = xs[(cc + 0) * XROW + t];
        const float x01 = xs[(cc + 1) * XROW + t];
        const float x08 = xs[(cc + 8) * XROW + t];
        const float x09 = xs[(cc + 9) * XROW + t];

        // fill: start first ldsm, then compute acc init in the bubble
        uint32_t bhv[2][4], blv[2][4];
        uint4 wa[2], wb[2];               // W-SMEM prefetch, double-buffered
        ldsm_x4_t(bhv[0], hhi);
        ldsm_x4_t(blv[0], hlo);

        // acc init = W_hx*x_t + b_h (folded out of the epilogue)
        float DA0[4] = { fmaf(wxA0, x00, bhA0), fmaf(wxA0, x01, bhA0),
                         fmaf(wxA1, x00, bhA1), fmaf(wxA1, x01, bhA1) };
        float DA1[4] = { fmaf(wxA0, x08, bhA0), fmaf(wxA0, x09, bhA0),
                         fmaf(wxA1, x08, bhA1), fmaf(wxA1, x09, bhA1) };
        float DB0[4] = { fmaf(wxB0, x00, bhB0), fmaf(wxB0, x01, bhB0),
                         fmaf(wxB1, x00, bhB1), fmaf(wxB1, x01, bhB1) };
        float DB1[4] = { fmaf(wxB0, x08, bhB0), fmaf(wxB0, x09, bhB0),
                         fmaf(wxB1, x08, bhB1), fmaf(wxB1, x09, bhB1) };

        #pragma unroll
        for (int kk = 0; kk < 16; ++kk) {
            const int cu = kk & 1, nx = cu ^ 1;
            if (kk < 15) {
                ldsm_x4_t(bhv[nx], hhi + (uint32_t)(kk + 1) * (16 * HROW));
                ldsm_x4_t(blv[nx], hlo + (uint32_t)(kk + 1) * (16 * HROW));
            }
            if (kk >= 7 && kk < 15) {     // prefetch W_lo[kk+1] into the OTHER buf
                wa[nx] = *reinterpret_cast<const uint4*>(wloSA + (kk - 7) * 512);
                wb[nx] = *reinterpret_cast<const uint4*>(wloSB + (kk - 7) * 512);
            }
            uint32_t wloA[4], wloB[4];
            if (kk < 8) {
                wloA[0] = wloR[kk*4+0]; wloA[1] = wloR[kk*4+1];
                wloA[2] = wloR[kk*4+2]; wloA[3] = wloR[kk*4+3];
                wloB[0] = wloR[32+kk*4+0]; wloB[1] = wloR[32+kk*4+1];
                wloB[2] = wloR[32+kk*4+2]; wloB[3] = wloR[32+kk*4+3];
            } else {
                wloA[0]=wa[cu].x; wloA[1]=wa[cu].y; wloA[2]=wa[cu].z; wloA[3]=wa[cu].w;
                wloB[0]=wb[cu].x; wloB[1]=wb[cu].y; wloB[2]=wb[cu].z; wloB[3]=wb[cu].w;
            }
            const uint32_t* aA = whi + kk * 4;
            const uint32_t* aB = whi + 64 + kk * 4;
            const uint32_t* bh4 = bhv[cu];
            const uint32_t* bl4 = blv[cu];

            mma16816(DA0, aA,   bh4[0], bh4[1]);
            mma16816(DA0, aA,   bl4[0], bl4[1]);
            mma16816(DA0, wloA, bh4[0], bh4[1]);
            mma16816(DA1, aA,   bh4[2], bh4[3]);
            mma16816(DA1, aA,   bl4[2], bl4[3]);
            mma16816(DA1, wloA, bh4[2], bh4[3]);
            mma16816(DB0, aB,   bh4[0], bh4[1]);
            mma16816(DB0, aB,   bl4[0], bl4[1]);
            mma16816(DB0, wloB, bh4[0], bh4[1]);
            mma16816(DB1, aB,   bh4[2], bh4[3]);
            mma16816(DB1, aB,   bl4[2], bl4[3]);
            mma16816(DB1, wloB, bh4[2], bh4[3]);
        }

        // ---- epilogue: tanh4 + split + STS ----
        tanh4(DA0);
        tanh4(DA1);
        tanh4(DB0);
        tanh4(DB1);

        char* ohi = sm + HB_OFF + (p ^ 1) * 2 * HTILE;
        char* olo = ohi + HTILE;
        uint32_t hi, lo;

        hi = split2(DA0[0], DA0[1], lo);
        *reinterpret_cast<uint32_t*>(ohi + rA0 * HROW + 4 * tIG) = hi;
        *reinterpret_cast<uint32_t*>(olo + rA0 * HROW + 4 * tIG) = lo;
        hi = split2(DA0[2], DA0[3], lo);
        *reinterpret_cast<uint32_t*>(ohi + rA1 * HROW + 4 * tIG) = hi;
        *reinterpret_cast<uint32_t*>(olo + rA1 * HROW + 4 * tIG) = lo;
        hi = split2(DA1[0], DA1[1], lo);
        *reinterpret_cast<uint32_t*>(ohi + rA0 * HROW + 16 + 4 * tIG) = hi;
        *reinterpret_cast<uint32_t*>(olo + rA0 * HROW + 16 + 4 * tIG) = lo;
        hi = split2(DA1[2], DA1[3], lo);
        *reinterpret_cast<uint32_t*>(ohi + rA1 * HROW + 16 + 4 * tIG) = hi;
        *reinterpret_cast<uint32_t*>(olo + rA1 * HROW + 16 + 4 * tIG) = lo;

        hi = split2(DB0[0], DB0[1], lo);
        *reinterpret_cast<uint32_t*>(ohi + rB0 * HROW + 4 * tIG) = hi;
        *reinterpret_cast<uint32_t*>(olo + rB0 * HROW + 4 * tIG) = lo;
        hi = split2(DB0[2], DB0[3], lo);
        *reinterpret_cast<uint32_t*>(ohi + rB1 * HROW + 4 * tIG) = hi;
        *reinterpret_cast<uint32_t*>(olo + rB1 * HROW + 4 * tIG) = lo;
        hi = split2(DB1[0], DB1[1], lo);
        *reinterpret_cast<uint32_t*>(ohi + rB0 * HROW + 16 + 4 * tIG) = hi;
        *reinterpret_cast<uint32_t*>(olo + rB0 * HROW + 16 + 4 * tIG) = lo;
        hi = split2(DB1[2], DB1[3], lo);
        *reinterpret_cast<uint32_t*>(ohi + rB1 * HROW + 16 + 4 * tIG) = hi;
        *reinterpret_cast<uint32_t*>(olo + rB1 * HROW + 16 + 4 * tIG) = lo;

        __syncthreads();
    }

    // ======================= final projection =======================
    if (tid < BT * CDIM) {
        const int b = tid / CDIM, c = tid % CDIM;
        const char* hb = sm + HB_OFF;
        const char* lb = hb + HTILE;
        float s = b_p[c];
        #pragma unroll 4
        for (int i = 0; i < HDIM; ++i) {
            float h = __bfloat162float(*reinterpret_cast<const __nv_bfloat16*>(
                          hb + i * HROW + 2 * b))
                    + __bfloat162float(*reinterpret_cast<const __nv_bfloat16*>(
                          lb + i * HROW + 2 * b));
            s += W_ph[c * HDIM + i] * h;
        }
        out[(size_t)(c0 + b) * CDIM + c] = s;
    }
}

extern "C" void kernel_launch(void* const* d_in, const int* in_sizes, int n_in,
                              void* d_out, int out_size)
{
    const float* x    = (const float*)d_in[0];
    const float* W_hx = (const float*)d_in[1];
    const float* W_hh = (const float*)d_in[2];
    const float* W_ph = (const float*)d_in[3];
    const float* b_h  = (const float*)d_in[4];
    const float* b_p  = (const float*)d_in[5];
    float* out = (float*)d_out;

    cudaFuncSetAttribute(rnn_hmma12_kernel,
                         cudaFuncAttributeMaxDynamicSharedMemorySize, SMEM_SZ);
    rnn_hmma12_kernel<<<NCTA, NTHR, SMEM_SZ>>>(x, W_hx, W_hh, W_ph, b_h, b_p, out);
}